// round 3
// baseline (speedup 1.0000x reference)
#include <cuda_runtime.h>
#include <float.h>
#include <math.h>

// CropRoi: f (4,64,32,32,32) f32; proposals (96,8) f32; out (96,64,7,7,7) f32.
// Box: c0 = max(floor((c-s/2)/4),0), c1 = min(ceil((c+s/2)/4),32); L in [2,14].
// Per-axis adaptive windows have size 1..3 and are always in-range, so the
// reference's clip+mask == plain max over the window.
//
// Launch 1 (precompute, 96 blocks): per proposal, channel-invariant data:
//   g_base[n]  = element offset of box corner inside f for channel 0
//   g_desc[n][o] = packed: 15-bit start offset within the 32^3 volume
//                  relative to corner, plus (size-1) per axis (2 bits each).
// Launch 2 (pool, grid 96 x 8): 8 channels per block, one thread per bin.
//   Desc decoded once; window walked once; 8 independent LDG/fmax chains
//   (channel stride 128KB) give MLP ~16 to hide L2 latency.

#define RBINS 7
#define NBINS (RBINS * RBINS * RBINS)   // 343
#define FDIM 32
#define MAXN 1024
#define CH 8                             // channels per block

__device__ int g_desc[MAXN * NBINS];
__device__ int g_base[MAXN];

__global__ void precompute_kernel(const float* __restrict__ props)
{
    const int n = blockIdx.x;
    const int o = threadIdx.x;
    const float* p = props + n * 8;

    int L[3];
#pragma unroll
    for (int ax = 0; ax < 3; ++ax) {
        const float ce = p[2 + ax], si = p[5 + ax];
        int lo = (int)floorf((ce - si * 0.5f) * 0.25f);
        int hi = (int)ceilf ((ce + si * 0.5f) * 0.25f);
        lo = max(lo, 0); hi = min(hi, FDIM);
        L[ax] = max(hi - lo, 0);
        if (o == 0 && ax == 0) {
            // compute full corner offset once (thread 0 handles ax loop too)
        }
    }

    if (o == 0) {
        const int b = (int)p[0];
        int c0[3];
#pragma unroll
        for (int ax = 0; ax < 3; ++ax) {
            const float ce = p[2 + ax], si = p[5 + ax];
            int lo = (int)floorf((ce - si * 0.5f) * 0.25f);
            c0[ax] = max(lo, 0);
        }
        g_base[n] = ((b * 64) << 15) + ((c0[0] * FDIM + c0[1]) * FDIM + c0[2]);
    }

    if (o < NBINS) {
        const int k = o % RBINS;
        const int j = (o / RBINS) % RBINS;
        const int i = o / (RBINS * RBINS);

        const int ds = (i * L[0]) / RBINS, de = ((i + 1) * L[0] + RBINS - 1) / RBINS;
        const int hs = (j * L[1]) / RBINS, he = ((j + 1) * L[1] + RBINS - 1) / RBINS;
        const int ws = (k * L[2]) / RBINS, we = ((k + 1) * L[2] + RBINS - 1) / RBINS;

        const int start = (ds * FDIM + hs) * FDIM + ws;          // 15 bits
        const int nd = de - ds - 1, nh = he - hs - 1, nw = we - ws - 1; // 0..2
        g_desc[n * NBINS + o] = start | (nd << 15) | (nh << 17) | (nw << 19);
    }
}

__global__ __launch_bounds__(352)
void pool_kernel(const float* __restrict__ f, float* __restrict__ out)
{
    const int n  = blockIdx.x;            // proposal
    const int cg = blockIdx.y;            // channel group (8 channels)
    const int o  = threadIdx.x;           // output bin
    if (o >= NBINS) return;

    const int desc = g_desc[n * NBINS + o];
    const int start = desc & 0x7FFF;
    const int nd = (desc >> 15) & 3;      // size-1 per axis (0..2)
    const int nh = (desc >> 17) & 3;
    const int nw = (desc >> 19) & 3;

    const float* base = f + g_base[n] + ((cg * CH) << 15) + start;

    float m0 = -FLT_MAX, m1 = -FLT_MAX, m2 = -FLT_MAX, m3 = -FLT_MAX;
    float m4 = -FLT_MAX, m5 = -FLT_MAX, m6 = -FLT_MAX, m7 = -FLT_MAX;

    for (int d = 0; d <= nd; ++d)
        for (int h = 0; h <= nh; ++h) {
            const float* row = base + (d * FDIM + h) * FDIM;
            for (int w = 0; w <= nw; ++w) {
                const float* e = row + w;
                m0 = fmaxf(m0, e[0 << 15]);
                m1 = fmaxf(m1, e[1 << 15]);
                m2 = fmaxf(m2, e[2 << 15]);
                m3 = fmaxf(m3, e[3 << 15]);
                m4 = fmaxf(m4, e[4 << 15]);
                m5 = fmaxf(m5, e[5 << 15]);
                m6 = fmaxf(m6, e[6 << 15]);
                m7 = fmaxf(m7, e[7 << 15]);
            }
        }

    float* op = out + ((size_t)(n * 64 + cg * CH)) * NBINS + o;
    op[0 * NBINS] = m0;
    op[1 * NBINS] = m1;
    op[2 * NBINS] = m2;
    op[3 * NBINS] = m3;
    op[4 * NBINS] = m4;
    op[5 * NBINS] = m5;
    op[6 * NBINS] = m6;
    op[7 * NBINS] = m7;
}

extern "C" void kernel_launch(void* const* d_in, const int* in_sizes, int n_in,
                              void* d_out, int out_size)
{
    const float* f     = (const float*)d_in[0];
    const float* props = (const float*)d_in[2];
    float* out = (float*)d_out;

    const int N = in_sizes[2] / 8;   // 96

    precompute_kernel<<<N, 352>>>(props);
    pool_kernel<<<dim3(N, 64 / CH), 352>>>(f, out);
}